// round 8
// baseline (speedup 1.0000x reference)
#include <cuda_runtime.h>

#define LROW 2048
#define NT   128          // threads per CTA
#define VPT  16           // elements per thread (NT*VPT == LROW)
#define NWARP (NT / 32)
#define LEPS 1e-10f
#define FULLM 0xFFFFFFFFu
#define MAXB 8192

__device__ float g_partials[MAXB];

// Bank swizzle for 64-bit smem words (VPT=16 blocked layout): conflict-free
// for the stride-16-word publish (bank = r ^ (lane&15)) and the partner reads
// (partner lanes within a 16-lane phase are a permutation).
__device__ __forceinline__ int SW(int i) { return i ^ ((i >> 4) & 15); }

// ascending-orderable bits of a float
__device__ __forceinline__ unsigned ordf(unsigned u) {
    return (u & 0x80000000u) ? ~u : (u ^ 0x80000000u);
}

__device__ __forceinline__ void ce(unsigned long long& x, unsigned long long& y, bool up) {
    if ((x > y) == up) { unsigned long long t = x; x = y; y = t; }
}

__device__ __forceinline__ unsigned long long shflx64(unsigned long long v, int m) {
    unsigned lo = (unsigned)v, hi = (unsigned)(v >> 32);
    lo = __shfl_xor_sync(FULLM, lo, m);
    hi = __shfl_xor_sync(FULLM, hi, m);
    return ((unsigned long long)hi << 32) | lo;
}

// One bitonic stage at element distance j = 16*m via warp shuffle:
// partner thread = tid ^ m, same register slot. Direction uniform (k >= 32).
__device__ __forceinline__ void shfl_stage(unsigned long long v[VPT], int tid, int m, bool up) {
    const bool takeMin = (((tid & m) == 0) == up);
    #pragma unroll
    for (int r = 0; r < VPT; r++) {
        unsigned long long p = shflx64(v[r], m);
        unsigned long long mn = v[r] < p ? v[r] : p;
        unsigned long long mx = v[r] < p ? p : v[r];
        v[r] = takeMin ? mn : mx;
    }
}

// One bitonic stage at element distance j = 16*m (m >= 32) via smem exchange:
// publish own slots, read partner's slots, keep min or max. No in-smem RMW.
__device__ __forceinline__ void smem_exchange_stage(unsigned long long v[VPT],
                                                    unsigned long long* keys,
                                                    int tid, int m, bool up) {
    __syncthreads();   // prior stage's partner reads complete before overwrite
    #pragma unroll
    for (int r = 0; r < VPT; r++) keys[SW(16 * tid + r)] = v[r];
    __syncthreads();
    const int ptid = tid ^ m;
    const bool takeMin = (((tid & m) == 0) == up);
    #pragma unroll
    for (int r = 0; r < VPT; r++) {
        unsigned long long p = keys[SW(16 * ptid + r)];
        unsigned long long mn = v[r] < p ? v[r] : p;
        unsigned long long mx = v[r] < p ? p : v[r];
        v[r] = takeMin ? mn : mx;
    }
}

// In-register stages j = 8,4,2,1 with direction uniform per thread (k >= 16).
__device__ __forceinline__ void local_tail16(unsigned long long v[VPT], bool up) {
    #pragma unroll
    for (int j = 8; j >= 1; j >>= 1) {
        #pragma unroll
        for (int r = 0; r < VPT; r++)
            if ((r & j) == 0) ce(v[r], v[r | j], up);
    }
}

__global__ __launch_bounds__(NT, 6)
void listmle_kernel(const float* __restrict__ preds,
                    const float* __restrict__ targs)
{
    __shared__ unsigned long long keys[LROW];   // 16 KB
    __shared__ float wred[NWARP];

    const int tid  = threadIdx.x;
    const int lane = tid & 31;
    const int warp = tid >> 5;
    const size_t base = (size_t)blockIdx.x * LROW;

    // ---- Load & build keys; accumulate sum of raw preds (linear loss term) ----
    unsigned long long v[VPT];
    float psum = 0.0f;   // sum over this thread's raw predictions
    {
        const float4* t4 = (const float4*)(targs + base);
        const float4* p4 = (const float4*)(preds + base);
        #pragma unroll
        for (int q = 0; q < 4; q++) {
            float4 tq = t4[4 * tid + q];
            float4 pq = p4[4 * tid + q];
            float tv[4] = {tq.x, tq.y, tq.z, tq.w};
            float pv[4] = {pq.x, pq.y, pq.z, pq.w};
            #pragma unroll
            for (int c = 0; c < 4; c++) {
                psum += pv[c];
                unsigned kt = ~ordf(__float_as_uint(tv[c]));  // ascending == descending target
                unsigned kp =  ordf(__float_as_uint(pv[c]));  // payload (tie-break by pred)
                v[4 * q + c] = ((unsigned long long)kt << 32) | kp;
            }
        }
    }

    // ---- Bitonic sort, ascending. Thread owns elements g = 16*tid + r (blocked). ----
    // k = 2,4,8: direction depends on r only -> fully in-register.
    #pragma unroll
    for (int k = 2; k <= 8; k <<= 1) {
        #pragma unroll
        for (int j = k >> 1; j >= 1; j >>= 1) {
            #pragma unroll
            for (int r = 0; r < VPT; r++)
                if ((r & j) == 0) ce(v[r], v[r | j], (r & k) == 0);
        }
    }
    // k = 16: direction uniform per thread
    local_tail16(v, (tid & 1) == 0);

    // k = 32..512: shuffle stages (j = k/2..16) then register tail
    #pragma unroll 1
    for (int k = 32; k <= 512; k <<= 1) {
        const bool up = ((tid & (k >> 4)) == 0);
        for (int j = k >> 1; j >= 16; j >>= 1) shfl_stage(v, tid, j >> 4, up);
        local_tail16(v, up);
    }

    // k = 1024: j=512 via smem exchange, then shuffle + register tail
    {
        const bool up = ((tid & 64) == 0);
        smem_exchange_stage(v, keys, tid, 32, up);
        #pragma unroll
        for (int j = 256; j >= 16; j >>= 1) shfl_stage(v, tid, j >> 4, up);
        local_tail16(v, up);
    }
    // k = 2048: j=1024,512 via smem exchange, then shuffle + register tail
    {
        const bool up = true;
        smem_exchange_stage(v, keys, tid, 64, up);
        smem_exchange_stage(v, keys, tid, 32, up);
        #pragma unroll
        for (int j = 256; j >= 16; j >>= 1) shfl_stage(v, tid, j >> 4, up);
        local_tail16(v, up);
    }

    // ---- Suffix sum of exp over sorted order (pos g = 16*tid + r) ----
    float e[VPT];
    #pragma unroll
    for (int r = 0; r < VPT; r++) {
        unsigned pv = (unsigned)v[r];
        unsigned pu = (pv & 0x80000000u) ? (pv ^ 0x80000000u) : ~pv;  // decode orderable
        e[r] = __expf(__uint_as_float(pu));
    }
    float run = 0.0f;
    #pragma unroll
    for (int r = 0; r < VPT; r++) run += e[r];      // thread total

    // inclusive suffix scan of thread totals within warp (higher lane = later pos)
    float sx = run;
    #pragma unroll
    for (int off = 1; off < 32; off <<= 1) {
        float y = __shfl_down_sync(FULLM, sx, off);
        if (lane < 32 - off) sx += y;
    }
    if (lane == 0) wred[warp] = sx;                 // warp total
    __syncthreads();
    float after = sx - run;                         // later threads in this warp
    #pragma unroll
    for (int w = 0; w < NWARP; w++)
        if (w > warp) after += wred[w];             // later warps

    // loss = sum_r log(denom_r + EPS) - sum_r p_r   (outer EPS dropped: <=2e-6 rel)
    float loss = 0.0f;
    float acc = after;
    #pragma unroll
    for (int r = VPT - 1; r >= 0; r--) {
        acc += e[r];                                // denom at pos 16*tid + r
        loss += __logf(acc + LEPS);
    }
    loss -= psum;

    // ---- Block reduce -> deterministic per-row partial ----
    #pragma unroll
    for (int off = 16; off; off >>= 1) loss += __shfl_xor_sync(FULLM, loss, off);
    __syncthreads();                                // wred suffix reads complete
    if (lane == 0) wred[warp] = loss;
    __syncthreads();
    if (tid == 0) {
        float tot = 0.0f;
        #pragma unroll
        for (int w = 0; w < NWARP; w++) tot += wred[w];
        g_partials[blockIdx.x] = tot;
    }
}

// Deterministic final reduction (fixed order, no atomics).
__global__ void reduce_kernel(float* __restrict__ out, int B, float invB)
{
    __shared__ float s[1024];
    const int t = threadIdx.x;
    float a = 0.0f;
    for (int i = t; i < B; i += 1024) a += g_partials[i];
    s[t] = a;
    __syncthreads();
    #pragma unroll
    for (int off = 512; off; off >>= 1) {
        if (t < off) s[t] += s[t + off];
        __syncthreads();
    }
    if (t == 0) out[0] = s[0] * invB;
}

extern "C" void kernel_launch(void* const* d_in, const int* in_sizes, int n_in,
                              void* d_out, int out_size)
{
    const float* preds = (const float*)d_in[0];
    const float* targs = (const float*)d_in[1];
    float* out = (float*)d_out;

    const int B = in_sizes[0] / LROW;

    listmle_kernel<<<B, NT>>>(preds, targs);
    reduce_kernel<<<1, 1024>>>(out, B, 1.0f / (float)B);
}